// round 13
// baseline (speedup 1.0000x reference)
#include <cuda_runtime.h>
#include <cstdint>

// Problem constants
#define BS   64
#define IC   256     // in_dim
#define NPIX 256     // pixels (I)
#define J    64      // out caps
#define D2   32      // dim per cap
#define NCHK 8       // i-chunks per batch in YD
#define CW   32      // chunk width (pixels)

// Global scratch (pred never materialized)
__device__ float g_L[(size_t)BS * J * NPIX];            // logits after iter-1
__device__ float g_xT[(size_t)BS * NPIX * IC];          // x transposed [b][i][ic]
__device__ float g_ypart[(size_t)BS * NCHK * J * IC];   // [b][ch][j][ic]
__device__ float g_cpart[(size_t)BS * NCHK * J];        // [b][ch][j]
__device__ float g_wt[(size_t)BS * J * IC];             // [b][j][ic]
__device__ float g_beta[(size_t)BS * J];                // [b][j]

// ---------------------------------------------------------------------------
// f32x2 helpers
// ---------------------------------------------------------------------------
#define FFMA2(acc, aa, bb) \
    asm("fma.rn.f32x2 %0, %1, %2, %0;" : "+l"(acc) : "l"(aa), "l"(bb))
__device__ __forceinline__ unsigned long long dup2f(float s) {
    unsigned long long d;
    asm("mov.b64 %0, {%1, %1};" : "=l"(d) : "f"(s));
    return d;
}
__device__ __forceinline__ float2 unpk(unsigned long long v) {
    float2 r;
    asm("mov.b64 {%0, %1}, %2;" : "=f"(r.x), "=f"(r.y) : "l"(v));
    return r;
}

// SMEM float offsets for yd_kernel (total 20672 floats = 82,688 B -> 2 CTAs/SM)
#define CSP    68                     // cs row stride (mult of 4: aligned float4)
#define XS_O   0                      // xs [ic=256][i=32]     8192
#define XT_O   8192                   // xT [i=32][ic=256]     8192
#define CS_O   16384                  // cs [i=32][j pad 68]   2176
#define LC_O   (CS_O + CW * CSP)      // Lc [j=64][i pad 33]   2112
#define SM_FLOATS (LC_O + J * 33)

// ---------------------------------------------------------------------------
// Prep: transpose x[b][ic][i] -> g_xT[b][i][ic]  (runs once)
// ---------------------------------------------------------------------------
__global__ __launch_bounds__(256) void xt_prep(const float* __restrict__ x) {
    __shared__ float t[32][33];
    int b = blockIdx.z, i0 = blockIdx.x * 32, ic0 = blockIdx.y * 32;
    int tx = threadIdx.x, ty = threadIdx.y;   // 32 x 8
    #pragma unroll
    for (int q = 0; q < 4; q++)
        t[ty + q * 8][tx] = x[((size_t)b * IC + ic0 + ty + q * 8) * NPIX + i0 + tx];
    __syncthreads();
    #pragma unroll
    for (int q = 0; q < 4; q++) {
        int row = ty + q * 8;
        g_xT[((size_t)b * NPIX + i0 + row) * IC + ic0 + tx] = t[tx][row];
    }
}

// ---------------------------------------------------------------------------
// YD kernel: one CTA per (i-chunk of 32, b), 512 threads, 2 CTAs/SM.
// it==0:  Lc = b_init;                          softmax; y partials
// it==1:  db = wt.x+beta; L=b_init+db (-> g_L); softmax; y partials
// it==2:  db = wt.x+beta; L=g_L+db;             softmax; y partials
// wt is streamed from global (not staged) to keep smem small.
// ---------------------------------------------------------------------------
__global__ __launch_bounds__(512, 2) void yd_kernel(
    const float* __restrict__ x, const float* __restrict__ b_init, int it)
{
    extern __shared__ float sm[];
    float* xs = sm + XS_O;
    float* xT = sm + XT_O;
    float* cs = sm + CS_O;
    float* Lc = sm + LC_O;

    const int ch  = blockIdx.x;
    const int b   = blockIdx.y;
    const int i0g = ch * CW;
    const int tid = threadIdx.x;

    // ---- loads (coalesced) ----
    const float* xb = x + (size_t)b * IC * NPIX + i0g;
    for (int e = tid; e < IC * CW; e += 512) {
        int ic = e >> 5, il = e & 31;
        xs[ic * CW + il] = xb[(size_t)ic * NPIX + il];
    }
    const float* xTb = g_xT + ((size_t)b * NPIX + i0g) * IC;
    for (int e = tid; e < CW * IC; e += 512)
        xT[e] = xTb[e];
    if (!it) {
        for (int e = tid; e < J * CW; e += 512) {
            int j = e >> 5, il = e & 31;
            Lc[j * 33 + il] = b_init[((size_t)b * J + j) * NPIX + i0g + il];
        }
    }
    __syncthreads();

    // ---- db GEMM: M=64(j) x N=32(i), K=256(ic); tile 2j x 2i, wt from global
    if (it) {
        const int ty = tid >> 4, tx = tid & 15;   // ty 0..31, tx 0..15
        const int j0 = ty * 2, il0 = tx * 2;
        unsigned long long acc0 = 0ull, acc1 = 0ull;
        const float4* w0q = reinterpret_cast<const float4*>(
            g_wt + ((size_t)b * J + j0) * IC);
        const float4* w1q = w0q + (IC / 4);
        #pragma unroll 4
        for (int k4 = 0; k4 < IC / 4; k4++) {
            float4 w0 = w0q[k4];
            float4 w1 = w1q[k4];
            const float* xrow = xs + (k4 * 4) * CW + il0;
            unsigned long long b0 = *reinterpret_cast<const unsigned long long*>(xrow);
            unsigned long long b1 = *reinterpret_cast<const unsigned long long*>(xrow + CW);
            unsigned long long b2 = *reinterpret_cast<const unsigned long long*>(xrow + 2 * CW);
            unsigned long long b3 = *reinterpret_cast<const unsigned long long*>(xrow + 3 * CW);
            FFMA2(acc0, dup2f(w0.x), b0); FFMA2(acc1, dup2f(w1.x), b0);
            FFMA2(acc0, dup2f(w0.y), b1); FFMA2(acc1, dup2f(w1.y), b1);
            FFMA2(acc0, dup2f(w0.z), b2); FFMA2(acc1, dup2f(w1.z), b2);
            FFMA2(acc0, dup2f(w0.w), b3); FFMA2(acc1, dup2f(w1.w), b3);
        }
        const float* Lsrc = (it == 2) ? g_L : b_init;
        #pragma unroll
        for (int r = 0; r < 2; r++) {
            int j = j0 + r;
            float be = g_beta[b * J + j];
            const float* Ls = Lsrc + ((size_t)b * J + j) * NPIX + i0g + il0;
            float2 lv = *reinterpret_cast<const float2*>(Ls);
            float2 dv = unpk(r == 0 ? acc0 : acc1);
            float l0 = lv.x + dv.x + be;
            float l1 = lv.y + dv.y + be;
            Lc[j * 33 + il0]     = l0;
            Lc[j * 33 + il0 + 1] = l1;
            if (it == 1) {
                float* Lg = g_L + ((size_t)b * J + j) * NPIX + i0g + il0;
                Lg[0] = l0; Lg[1] = l1;
            }
        }
        __syncthreads();
    }

    // ---- softmax over j per pixel: one warp per 2 pixels, 2 j per lane ----
    {
        int w = tid >> 5, lane = tid & 31;
        #pragma unroll
        for (int h = 0; h < 2; h++) {
            int i = w * 2 + h;
            float v0 = Lc[(2 * lane) * 33 + i];
            float v1 = Lc[(2 * lane + 1) * 33 + i];
            float m = fmaxf(v0, v1);
            #pragma unroll
            for (int o = 16; o; o >>= 1)
                m = fmaxf(m, __shfl_xor_sync(0xFFFFFFFFu, m, o));
            float e0 = __expf(v0 - m), e1 = __expf(v1 - m);
            float ssum = e0 + e1;
            #pragma unroll
            for (int o = 16; o; o >>= 1)
                ssum += __shfl_xor_sync(0xFFFFFFFFu, ssum, o);
            float rd = 1.0f / ssum;
            cs[i * CSP + 2 * lane]     = e0 * rd;
            cs[i * CSP + 2 * lane + 1] = e1 * rd;
        }
    }
    __syncthreads();

    // ---- Csum partial per j ----
    if (tid < J) {
        float cc = 0.f;
        #pragma unroll 8
        for (int i2 = 0; i2 < CW; i2++) cc += cs[i2 * CSP + tid];
        g_cpart[((size_t)b * NCHK + ch) * J + tid] = cc;
    }

    // ---- y GEMM: M=64(j) x N=256(ic), K=32(i); tile 4j x 8ic ----
    {
        const int ty = tid >> 5, tx = tid & 31;   // ty 0..15, tx 0..31
        const int j0 = ty * 4, ic0 = tx * 8;
        unsigned long long acc[4][4];
        #pragma unroll
        for (int r = 0; r < 4; r++)
            #pragma unroll
            for (int p = 0; p < 4; p++) acc[r][p] = 0ull;

        #pragma unroll 2
        for (int k = 0; k < CW; k++) {
            float4 c4 = *reinterpret_cast<const float4*>(cs + k * CSP + j0);
            const unsigned long long* bq =
                reinterpret_cast<const unsigned long long*>(xT + k * 256 + ic0);
            unsigned long long b0 = bq[0], b1 = bq[1], b2 = bq[2], b3 = bq[3];
            unsigned long long ad;
            ad = dup2f(c4.x);
            FFMA2(acc[0][0], ad, b0); FFMA2(acc[0][1], ad, b1);
            FFMA2(acc[0][2], ad, b2); FFMA2(acc[0][3], ad, b3);
            ad = dup2f(c4.y);
            FFMA2(acc[1][0], ad, b0); FFMA2(acc[1][1], ad, b1);
            FFMA2(acc[1][2], ad, b2); FFMA2(acc[1][3], ad, b3);
            ad = dup2f(c4.z);
            FFMA2(acc[2][0], ad, b0); FFMA2(acc[2][1], ad, b1);
            FFMA2(acc[2][2], ad, b2); FFMA2(acc[2][3], ad, b3);
            ad = dup2f(c4.w);
            FFMA2(acc[3][0], ad, b0); FFMA2(acc[3][1], ad, b1);
            FFMA2(acc[3][2], ad, b2); FFMA2(acc[3][3], ad, b3);
        }
        float* ybase = g_ypart + (((size_t)b * NCHK + ch) * J + j0) * IC + ic0;
        #pragma unroll
        for (int r = 0; r < 4; r++) {
            float* yr = ybase + (size_t)r * IC;
            #pragma unroll
            for (int p = 0; p < 2; p++) {
                float2 e0 = unpk(acc[r][2 * p]);
                float2 e1 = unpk(acc[r][2 * p + 1]);
                *reinterpret_cast<float4*>(yr + p * 4) =
                    make_float4(e0.x, e0.y, e1.x, e1.y);
            }
        }
    }
}

// ---------------------------------------------------------------------------
// S kernel: one CTA per (j, 16-batch group), 256 threads.
// smem: Wj[32][260], ysm[16][260], vsm/ssm[16][33], Cs, Wbj.
// ---------------------------------------------------------------------------
#define WJ_O2   0
#define YS_O2   8320
#define VS_O2   12480
#define SS_O2   13008
#define CS_O2   13536
#define WB_O2   13552
#define S_SM_FLOATS 13584        // 54,336 B

__global__ __launch_bounds__(256) void s_kernel(
    const float* __restrict__ W, const float* __restrict__ Wb,
    float* __restrict__ out, int final_it)
{
    extern __shared__ float ss[];
    float* Wj  = ss + WJ_O2;
    float* ysm = ss + YS_O2;
    float* vsm = ss + VS_O2;
    float* ssm = ss + SS_O2;
    float* Cs  = ss + CS_O2;
    float* Wbj = ss + WB_O2;

    const int j   = blockIdx.x;
    const int b0  = blockIdx.y * 16;
    const int tid = threadIdx.x;

    // stage Wj (row-padded), y (chunk-reduced over 8), C, Wb
    for (int e = tid; e < D2 * IC; e += 256) {
        int d = e >> 8, ic = e & 255;
        Wj[d * 260 + ic] = W[(size_t)j * D2 * IC + e];
    }
    if (tid < D2) Wbj[tid] = Wb[j * D2 + tid];
    for (int e = tid; e < 16 * IC; e += 256) {
        int b = e >> 8, ic = e & 255;
        const float* yp = g_ypart + (((size_t)(b0 + b) * NCHK) * J + j) * IC + ic;
        float acc = 0.f;
        #pragma unroll
        for (int c = 0; c < NCHK; c++)
            acc += yp[(size_t)c * J * IC];
        ysm[b * 260 + ic] = acc;
    }
    if (tid < 16) {
        const float* cp = g_cpart + ((size_t)(b0 + tid) * NCHK) * J + j;
        float acc = 0.f;
        #pragma unroll
        for (int c = 0; c < NCHK; c++)
            acc += cp[(size_t)c * J];
        Cs[tid] = acc;
    }
    __syncthreads();

    // stage2: s[b][d] = Wj[d,:].y[b,:] + Wb[d]*C[b].  thread -> (b, d-pair)
    {
        int b = tid & 15, d0 = (tid >> 4) * 2;
        const float* y  = ysm + b * 260;
        const float* w0 = Wj + d0 * 260;
        const float* w1 = w0 + 260;
        float a0 = 0.f, a1 = 0.f;
        #pragma unroll 8
        for (int ic = 0; ic < IC; ic += 4) {
            float4 y4 = *reinterpret_cast<const float4*>(y + ic);
            float4 wa = *reinterpret_cast<const float4*>(w0 + ic);
            float4 wb = *reinterpret_cast<const float4*>(w1 + ic);
            a0 += y4.x * wa.x + y4.y * wa.y + y4.z * wa.z + y4.w * wa.w;
            a1 += y4.x * wb.x + y4.y * wb.y + y4.z * wb.z + y4.w * wb.w;
        }
        float C = Cs[b];
        ssm[b * 33 + d0]     = a0 + Wbj[d0] * C;
        ssm[b * 33 + d0 + 1] = a1 + Wbj[d0 + 1] * C;
    }
    __syncthreads();

    // squash: warp w handles b = 2w, 2w+1; lane = d
    {
        int w = tid >> 5, lane = tid & 31;
        #pragma unroll
        for (int h = 0; h < 2; h++) {
            int b = w * 2 + h;
            float sv = ssm[b * 33 + lane];
            float sq = sv * sv;
            #pragma unroll
            for (int o = 16; o; o >>= 1) sq += __shfl_xor_sync(0xFFFFFFFFu, sq, o);
            float scale = (sq / (1.0f + sq)) * rsqrtf(sq + 1e-8f);
            float vv = scale * sv;
            vsm[b * 33 + lane] = vv;
            if (final_it) out[((size_t)(b0 + b) * J + j) * D2 + lane] = vv;
            float bt = vv * Wbj[lane];
            #pragma unroll
            for (int o = 16; o; o >>= 1) bt += __shfl_xor_sync(0xFFFFFFFFu, bt, o);
            if (lane == 0) g_beta[(b0 + b) * J + j] = bt;
        }
    }
    __syncthreads();

    // stage4: wt[b][ic] = sum_d v[b][d] * Wj[d][ic].  thread = ic.
    if (!final_it) {
        int ic = tid;
        float wv[16];
        #pragma unroll
        for (int b = 0; b < 16; b++) wv[b] = 0.f;
        #pragma unroll 4
        for (int d = 0; d < D2; d++) {
            float wjv = Wj[d * 260 + ic];
            #pragma unroll
            for (int b = 0; b < 16; b++)
                wv[b] = fmaf(vsm[b * 33 + d], wjv, wv[b]);
        }
        #pragma unroll
        for (int b = 0; b < 16; b++)
            g_wt[((size_t)(b0 + b) * J + j) * IC + ic] = wv[b];
    }
}

// ---------------------------------------------------------------------------
// Launch (7 kernels, graph-capturable, allocation-free)
// Inputs: x[64,256,16,16] f32, b_init[64,64,256] f32, W[2048,256] f32, Wb[2048] f32
// Output: v[64,64,32] f32
// ---------------------------------------------------------------------------
extern "C" void kernel_launch(void* const* d_in, const int* in_sizes, int n_in,
                              void* d_out, int out_size)
{
    const float* x      = (const float*)d_in[0];
    const float* b_init = (const float*)d_in[1];
    const float* W      = (const float*)d_in[2];
    const float* Wb     = (const float*)d_in[3];
    float* out = (float*)d_out;

    const int ysmem = SM_FLOATS * (int)sizeof(float);     // 82,688 B
    const int ssmem = S_SM_FLOATS * (int)sizeof(float);   // 54,336 B
    cudaFuncSetAttribute(yd_kernel, cudaFuncAttributeMaxDynamicSharedMemorySize, ysmem);
    cudaFuncSetAttribute(s_kernel,  cudaFuncAttributeMaxDynamicSharedMemorySize, ssmem);

    xt_prep<<<dim3(NPIX / 32, IC / 32, BS), dim3(32, 8)>>>(x);

    dim3 ygrid(NCHK, BS);      // 8 x 64 = 512 CTAs, 2/SM
    dim3 sgrid(J, 4);          // 64 x 4  = 256 CTAs (16 b each)

    yd_kernel<<<ygrid, 512, ysmem>>>(x, b_init, 0);
    s_kernel<<<sgrid, 256, ssmem>>>(W, Wb, out, 0);
    yd_kernel<<<ygrid, 512, ysmem>>>(x, b_init, 1);
    s_kernel<<<sgrid, 256, ssmem>>>(W, Wb, out, 0);
    yd_kernel<<<ygrid, 512, ysmem>>>(x, b_init, 2);
    s_kernel<<<sgrid, 256, ssmem>>>(W, Wb, out, 1);
}

// round 14
// speedup vs baseline: 1.1714x; 1.1714x over previous
#include <cuda_runtime.h>
#include <cstdint>

// Problem constants
#define BS   64
#define IC   256     // in_dim
#define NPIX 256     // pixels (I)
#define J    64      // out caps
#define D2   32      // dim per cap
#define NCHK 4       // i-chunks per batch in YD
#define CW   64      // chunk width (pixels)

// Global scratch
__device__ float g_L[(size_t)BS * J * NPIX];            // logits after iter-1
__device__ float g_xT[(size_t)BS * NPIX * IC];          // x transposed [b][i][ic]
__device__ float g_ypart[(size_t)BS * NCHK * J * IC];   // [b][ch][j][ic]
__device__ float g_cpart[(size_t)BS * NCHK * J];        // [b][ch][j]
__device__ float g_wtT[(size_t)BS * IC * J];            // [b][ic][j]  (transposed!)
__device__ float g_beta[(size_t)BS * J];                // [b][j]

// ---------------------------------------------------------------------------
// f32x2 helpers
// ---------------------------------------------------------------------------
#define FFMA2(acc, aa, bb) \
    asm("fma.rn.f32x2 %0, %1, %2, %0;" : "+l"(acc) : "l"(aa), "l"(bb))
__device__ __forceinline__ unsigned long long dup2f(float s) {
    unsigned long long d;
    asm("mov.b64 %0, {%1, %1};" : "=l"(d) : "f"(s));
    return d;
}
__device__ __forceinline__ float2 unpk(unsigned long long v) {
    float2 r;
    asm("mov.b64 {%0, %1}, %2;" : "=f"(r.x), "=f"(r.y) : "l"(v));
    return r;
}

// SMEM float offsets for yd_kernel (230,656 B total)
#define CSP    68                     // cs row stride (mult of 4)
#define XS_O   0                      // xs  [ic=256][i=64]     16384
#define XT_O   16384                  // xT  [i=64][ic=256]     16384
#define WT_O   32768                  // wrT [ic=256][j=64]     16384
#define CS_O   49152                  // cs  [i=64][j pad 68]   4352
#define LC_O   (CS_O + CW * CSP)      // Lc  [j=64][i pad 65]   4160
#define SM_FLOATS (LC_O + J * 65)     // 57664 floats

// ---------------------------------------------------------------------------
// Prep: transpose x[b][ic][i] -> g_xT[b][i][ic]  (runs once)
// ---------------------------------------------------------------------------
__global__ __launch_bounds__(256) void xt_prep(const float* __restrict__ x) {
    __shared__ float t[32][33];
    int b = blockIdx.z, i0 = blockIdx.x * 32, ic0 = blockIdx.y * 32;
    int tx = threadIdx.x, ty = threadIdx.y;   // 32 x 8
    #pragma unroll
    for (int q = 0; q < 4; q++)
        t[ty + q * 8][tx] = x[((size_t)b * IC + ic0 + ty + q * 8) * NPIX + i0 + tx];
    __syncthreads();
    #pragma unroll
    for (int q = 0; q < 4; q++) {
        int row = ty + q * 8;
        g_xT[((size_t)b * NPIX + i0 + row) * IC + ic0 + tx] = t[tx][row];
    }
}

// ---------------------------------------------------------------------------
// YD kernel: one CTA per (i-chunk of 64, b), 512 threads, 1 CTA/SM.
// GEMMs mapped lane=j with fat operand broadcast (crossbar-minimal).
// ---------------------------------------------------------------------------
__global__ __launch_bounds__(512, 1) void yd_kernel(
    const float* __restrict__ x, const float* __restrict__ b_init, int it)
{
    extern __shared__ float sm[];
    float* xs  = sm + XS_O;
    float* xT  = sm + XT_O;
    float* wrT = sm + WT_O;
    float* cs  = sm + CS_O;
    float* Lc  = sm + LC_O;

    const int ch   = blockIdx.x;
    const int b    = blockIdx.y;
    const int i0g  = ch * CW;
    const int tid  = threadIdx.x;
    const int w    = tid >> 5;
    const int lane = tid & 31;

    // ---- loads (coalesced) ----
    const float* xb = x + (size_t)b * IC * NPIX + i0g;
    for (int e = tid; e < IC * CW; e += 512) {
        int ic = e >> 6, il = e & 63;
        xs[ic * CW + il] = xb[(size_t)ic * NPIX + il];
    }
    const float* xTb = g_xT + ((size_t)b * NPIX + i0g) * IC;
    for (int e = tid; e < CW * IC; e += 512)
        xT[e] = xTb[e];
    if (it) {
        const float* wsrc = g_wtT + (size_t)b * IC * J;
        for (int e = tid; e < IC * J; e += 512)
            wrT[e] = wsrc[e];
    } else {
        for (int e = tid; e < J * CW; e += 512) {
            int j = e >> 6, il = e & 63;
            Lc[j * 65 + il] = b_init[((size_t)b * J + j) * NPIX + i0g + il];
        }
    }
    __syncthreads();

    // ---- db GEMM: db[j][i] = sum_ic wrT[ic][j]*xs[ic][i], j-pair packed ----
    // warp = (ihalf, jblock of 8); lane = i within half.
    if (it) {
        const int ihalf = w & 1, jb = (w >> 1) * 8;
        const int il = ihalf * 32 + lane;
        unsigned long long acc[4] = {0ull, 0ull, 0ull, 0ull};
        #pragma unroll 4
        for (int ic = 0; ic < IC; ic++) {
            unsigned long long xd = dup2f(xs[ic * CW + il]);   // lane-distinct
            const ulonglong2* wp =
                reinterpret_cast<const ulonglong2*>(wrT + ic * J + jb);  // bcast
            ulonglong2 w01 = wp[0], w23 = wp[1];
            FFMA2(acc[0], w01.x, xd);
            FFMA2(acc[1], w01.y, xd);
            FFMA2(acc[2], w23.x, xd);
            FFMA2(acc[3], w23.y, xd);
        }
        const float* Lsrc = (it == 2) ? g_L : b_init;
        #pragma unroll
        for (int p = 0; p < 4; p++) {
            int j = jb + 2 * p;
            float2 dv = unpk(acc[p]);
            float be0 = g_beta[b * J + j];
            float be1 = g_beta[b * J + j + 1];
            float l0 = Lsrc[((size_t)b * J + j) * NPIX + i0g + il] + dv.x + be0;
            float l1 = Lsrc[((size_t)b * J + j + 1) * NPIX + i0g + il] + dv.y + be1;
            Lc[j * 65 + il]       = l0;
            Lc[(j + 1) * 65 + il] = l1;
            if (it == 1) {
                g_L[((size_t)b * J + j) * NPIX + i0g + il]     = l0;
                g_L[((size_t)b * J + j + 1) * NPIX + i0g + il] = l1;
            }
        }
        __syncthreads();
    }

    // ---- softmax over j per pixel: 8 threads per pixel, shfl reduce ----
    {
        int i = tid >> 3, sub = tid & 7, jb2 = sub * 8;
        float m = -1e30f;
        #pragma unroll
        for (int jj = 0; jj < 8; jj++)
            m = fmaxf(m, Lc[(jb2 + jj) * 65 + i]);
        #pragma unroll
        for (int o = 1; o < 8; o <<= 1)
            m = fmaxf(m, __shfl_xor_sync(0xFFFFFFFFu, m, o));
        float ssum = 0.f;
        #pragma unroll
        for (int jj = 0; jj < 8; jj++) {
            float e = __expf(Lc[(jb2 + jj) * 65 + i] - m);
            cs[i * CSP + jb2 + jj] = e;
            ssum += e;
        }
        #pragma unroll
        for (int o = 1; o < 8; o <<= 1)
            ssum += __shfl_xor_sync(0xFFFFFFFFu, ssum, o);
        float rd = 1.0f / ssum;
        #pragma unroll
        for (int jj = 0; jj < 8; jj++)
            cs[i * CSP + jb2 + jj] *= rd;
    }
    __syncthreads();

    // ---- Csum partial per j ----
    if (tid < J) {
        float cc = 0.f;
        #pragma unroll 8
        for (int i2 = 0; i2 < CW; i2++) cc += cs[i2 * CSP + tid];
        g_cpart[((size_t)b * NCHK + ch) * J + tid] = cc;
    }

    // ---- y GEMM: y[j][ic] = sum_i cs[i][j]*xT[i][ic], ic-pair packed ----
    // warp = 16-ic block; lane = j (2 j per lane: lane, lane+32).
    {
        const int ic0 = w * 16;
        unsigned long long acc[2][8];
        #pragma unroll
        for (int h = 0; h < 2; h++)
            #pragma unroll
            for (int p = 0; p < 8; p++) acc[h][p] = 0ull;

        #pragma unroll 2
        for (int k = 0; k < CW; k++) {
            unsigned long long cd0 = dup2f(cs[k * CSP + lane]);        // distinct
            unsigned long long cd1 = dup2f(cs[k * CSP + lane + 32]);   // distinct
            const ulonglong2* xq =
                reinterpret_cast<const ulonglong2*>(xT + k * 256 + ic0);  // bcast
            ulonglong2 x01 = xq[0], x23 = xq[1], x45 = xq[2], x67 = xq[3];
            FFMA2(acc[0][0], cd0, x01.x); FFMA2(acc[0][1], cd0, x01.y);
            FFMA2(acc[0][2], cd0, x23.x); FFMA2(acc[0][3], cd0, x23.y);
            FFMA2(acc[0][4], cd0, x45.x); FFMA2(acc[0][5], cd0, x45.y);
            FFMA2(acc[0][6], cd0, x67.x); FFMA2(acc[0][7], cd0, x67.y);
            FFMA2(acc[1][0], cd1, x01.x); FFMA2(acc[1][1], cd1, x01.y);
            FFMA2(acc[1][2], cd1, x23.x); FFMA2(acc[1][3], cd1, x23.y);
            FFMA2(acc[1][4], cd1, x45.x); FFMA2(acc[1][5], cd1, x45.y);
            FFMA2(acc[1][6], cd1, x67.x); FFMA2(acc[1][7], cd1, x67.y);
        }
        #pragma unroll
        for (int h = 0; h < 2; h++) {
            int j = lane + 32 * h;
            float* yr = g_ypart + (((size_t)b * NCHK + ch) * J + j) * IC + ic0;
            #pragma unroll
            for (int q = 0; q < 4; q++) {
                float2 e0 = unpk(acc[h][2 * q]);
                float2 e1 = unpk(acc[h][2 * q + 1]);
                *reinterpret_cast<float4*>(yr + 4 * q) =
                    make_float4(e0.x, e0.y, e1.x, e1.y);
            }
        }
    }
}

// ---------------------------------------------------------------------------
// S kernel: one CTA per (j, 16-batch group), 256 threads.
// Writes g_wtT transposed ([b][ic][j]) so yd needs no transpose.
// ---------------------------------------------------------------------------
#define WJ_O2   0
#define YS_O2   8320
#define VS_O2   12480
#define SS_O2   13008
#define CS_O2   13536
#define WB_O2   13552
#define S_SM_FLOATS 13584        // 54,336 B

__global__ __launch_bounds__(256) void s_kernel(
    const float* __restrict__ W, const float* __restrict__ Wb,
    float* __restrict__ out, int final_it)
{
    extern __shared__ float ss[];
    float* Wj  = ss + WJ_O2;
    float* ysm = ss + YS_O2;
    float* vsm = ss + VS_O2;
    float* ssm = ss + SS_O2;
    float* Cs  = ss + CS_O2;
    float* Wbj = ss + WB_O2;

    const int j   = blockIdx.x;
    const int b0  = blockIdx.y * 16;
    const int tid = threadIdx.x;

    for (int e = tid; e < D2 * IC; e += 256) {
        int d = e >> 8, ic = e & 255;
        Wj[d * 260 + ic] = W[(size_t)j * D2 * IC + e];
    }
    if (tid < D2) Wbj[tid] = Wb[j * D2 + tid];
    for (int e = tid; e < 16 * IC; e += 256) {
        int b = e >> 8, ic = e & 255;
        const float* yp = g_ypart + (((size_t)(b0 + b) * NCHK) * J + j) * IC + ic;
        ysm[b * 260 + ic] = (yp[0] + yp[(size_t)J * IC])
                          + (yp[2 * (size_t)J * IC] + yp[3 * (size_t)J * IC]);
    }
    if (tid < 16) {
        const float* cp = g_cpart + ((size_t)(b0 + tid) * NCHK) * J + j;
        Cs[tid] = (cp[0] + cp[J]) + (cp[2 * J] + cp[3 * J]);
    }
    __syncthreads();

    // stage2: s[b][d] = Wj[d,:].y[b,:] + Wb[d]*C[b]
    {
        int b = tid & 15, d0 = (tid >> 4) * 2;
        const float* y  = ysm + b * 260;
        const float* w0 = Wj + d0 * 260;
        const float* w1 = w0 + 260;
        float a0 = 0.f, a1 = 0.f;
        #pragma unroll 8
        for (int ic = 0; ic < IC; ic += 4) {
            float4 y4 = *reinterpret_cast<const float4*>(y + ic);
            float4 wa = *reinterpret_cast<const float4*>(w0 + ic);
            float4 wb = *reinterpret_cast<const float4*>(w1 + ic);
            a0 += y4.x * wa.x + y4.y * wa.y + y4.z * wa.z + y4.w * wa.w;
            a1 += y4.x * wb.x + y4.y * wb.y + y4.z * wb.z + y4.w * wb.w;
        }
        float C = Cs[b];
        ssm[b * 33 + d0]     = a0 + Wbj[d0] * C;
        ssm[b * 33 + d0 + 1] = a1 + Wbj[d0 + 1] * C;
    }
    __syncthreads();

    // squash: warp w handles b = 2w, 2w+1; lane = d
    {
        int w = tid >> 5, lane = tid & 31;
        #pragma unroll
        for (int h = 0; h < 2; h++) {
            int b = w * 2 + h;
            float sv = ssm[b * 33 + lane];
            float sq = sv * sv;
            #pragma unroll
            for (int o = 16; o; o >>= 1) sq += __shfl_xor_sync(0xFFFFFFFFu, sq, o);
            float scale = (sq / (1.0f + sq)) * rsqrtf(sq + 1e-8f);
            float vv = scale * sv;
            vsm[b * 33 + lane] = vv;
            if (final_it) out[((size_t)(b0 + b) * J + j) * D2 + lane] = vv;
            float bt = vv * Wbj[lane];
            #pragma unroll
            for (int o = 16; o; o >>= 1) bt += __shfl_xor_sync(0xFFFFFFFFu, bt, o);
            if (lane == 0) g_beta[(b0 + b) * J + j] = bt;
        }
    }
    __syncthreads();

    // stage4: wtT[b][ic][j] = sum_d v[b][d] * Wj[d][ic].  thread = ic.
    if (!final_it) {
        int ic = tid;
        float wv[16];
        #pragma unroll
        for (int b = 0; b < 16; b++) wv[b] = 0.f;
        #pragma unroll 4
        for (int d = 0; d < D2; d++) {
            float wjv = Wj[d * 260 + ic];
            #pragma unroll
            for (int b = 0; b < 16; b++)
                wv[b] = fmaf(vsm[b * 33 + d], wjv, wv[b]);
        }
        #pragma unroll
        for (int b = 0; b < 16; b++)
            g_wtT[((size_t)(b0 + b) * IC + ic) * J + j] = wv[b];
    }
}

// ---------------------------------------------------------------------------
// Launch (7 kernels, graph-capturable, allocation-free)
// Inputs: x[64,256,16,16] f32, b_init[64,64,256] f32, W[2048,256] f32, Wb[2048] f32
// Output: v[64,64,32] f32
// ---------------------------------------------------------------------------
extern "C" void kernel_launch(void* const* d_in, const int* in_sizes, int n_in,
                              void* d_out, int out_size)
{
    const float* x      = (const float*)d_in[0];
    const float* b_init = (const float*)d_in[1];
    const float* W      = (const float*)d_in[2];
    const float* Wb     = (const float*)d_in[3];
    float* out = (float*)d_out;

    const int ysmem = SM_FLOATS * (int)sizeof(float);     // 230,656 B
    const int ssmem = S_SM_FLOATS * (int)sizeof(float);   // 54,336 B
    cudaFuncSetAttribute(yd_kernel, cudaFuncAttributeMaxDynamicSharedMemorySize, ysmem);
    cudaFuncSetAttribute(s_kernel,  cudaFuncAttributeMaxDynamicSharedMemorySize, ssmem);

    xt_prep<<<dim3(NPIX / 32, IC / 32, BS), dim3(32, 8)>>>(x);

    dim3 ygrid(NCHK, BS);      // 4 x 64 = 256 CTAs
    dim3 sgrid(J, 4);          // 64 x 4  = 256 CTAs

    yd_kernel<<<ygrid, 512, ysmem>>>(x, b_init, 0);
    s_kernel<<<sgrid, 256, ssmem>>>(W, Wb, out, 0);
    yd_kernel<<<ygrid, 512, ysmem>>>(x, b_init, 1);
    s_kernel<<<sgrid, 256, ssmem>>>(W, Wb, out, 0);
    yd_kernel<<<ygrid, 512, ysmem>>>(x, b_init, 2);
    s_kernel<<<sgrid, 256, ssmem>>>(W, Wb, out, 1);
}

// round 15
// speedup vs baseline: 1.2076x; 1.0309x over previous
#include <cuda_runtime.h>
#include <cstdint>

// Problem constants
#define BS   64
#define IC   256     // in_dim
#define NPIX 256     // pixels (I)
#define J    64      // out caps
#define D2   32      // dim per cap
#define NCHK 4       // i-chunks for sy / ypart
#define CW   64      // sy chunk width
#define CWD  32      // db chunk width

// Global scratch
__device__ float g_L[(size_t)BS * J * NPIX];            // working logits
__device__ float g_xT[(size_t)BS * NPIX * IC];          // x transposed [b][i][ic]
__device__ float g_ypart[(size_t)BS * NCHK * J * IC];   // [b][ch][j][ic]
__device__ float g_cpart[(size_t)BS * NCHK * J];        // [b][ch][j]
__device__ float g_wtT[(size_t)BS * IC * J];            // [b][ic][j]
__device__ float g_beta[(size_t)BS * J];                // [b][j]

// ---------------------------------------------------------------------------
// f32x2 helpers
// ---------------------------------------------------------------------------
#define FFMA2(acc, aa, bb) \
    asm("fma.rn.f32x2 %0, %1, %2, %0;" : "+l"(acc) : "l"(aa), "l"(bb))
__device__ __forceinline__ unsigned long long dup2f(float s) {
    unsigned long long d;
    asm("mov.b64 %0, {%1, %1};" : "=l"(d) : "f"(s));
    return d;
}
__device__ __forceinline__ float2 unpk(unsigned long long v) {
    float2 r;
    asm("mov.b64 {%0, %1}, %2;" : "=f"(r.x), "=f"(r.y) : "l"(v));
    return r;
}

// ---------------------------------------------------------------------------
// Prep: transpose x[b][ic][i] -> g_xT[b][i][ic]  (runs once)
// ---------------------------------------------------------------------------
__global__ __launch_bounds__(256) void xt_prep(const float* __restrict__ x) {
    __shared__ float t[32][33];
    int b = blockIdx.z, i0 = blockIdx.x * 32, ic0 = blockIdx.y * 32;
    int tx = threadIdx.x, ty = threadIdx.y;   // 32 x 8
    #pragma unroll
    for (int q = 0; q < 4; q++)
        t[ty + q * 8][tx] = x[((size_t)b * IC + ic0 + ty + q * 8) * NPIX + i0 + tx];
    __syncthreads();
    #pragma unroll
    for (int q = 0; q < 4; q++) {
        int row = ty + q * 8;
        g_xT[((size_t)b * NPIX + i0 + row) * IC + ic0 + tx] = t[tx][row];
    }
}

// ---------------------------------------------------------------------------
// db kernel (it1/it2): Lwork[b,j,i] (+)= sum_ic wrT[ic][j]*x[b,ic,i] + beta.
// Grid (8 chunks of 32 px, 64 b) = 512 CTAs, 256 thr, 96KB smem -> 2 CTAs/SM.
// Warp = 8-j block, lane = pixel. j-pairs packed in f32x2.
// ---------------------------------------------------------------------------
#define DB_SM_FLOATS (8192 + 16384)   // xs[256][32] + wrT[256][64] = 96 KB

__global__ __launch_bounds__(256, 2) void db_kernel(
    const float* __restrict__ x, const float* __restrict__ b_init, int it)
{
    extern __shared__ float sm[];
    float* xs  = sm;            // [ic][il]
    float* wrT = sm + 8192;     // [ic][j]

    const int ch   = blockIdx.x;
    const int b    = blockIdx.y;
    const int i0g  = ch * CWD;
    const int tid  = threadIdx.x;
    const int w    = tid >> 5;
    const int lane = tid & 31;

    // loads (float4, coalesced)
    const float* xb = x + (size_t)b * IC * NPIX + i0g;
    for (int e = tid; e < IC * (CWD / 4); e += 256) {
        int ic = e >> 3, q = e & 7;
        *reinterpret_cast<float4*>(xs + ic * CWD + q * 4) =
            *reinterpret_cast<const float4*>(xb + (size_t)ic * NPIX + q * 4);
    }
    const float4* wsrc = reinterpret_cast<const float4*>(g_wtT + (size_t)b * IC * J);
    float4* wdst = reinterpret_cast<float4*>(wrT);
    for (int e = tid; e < IC * J / 4; e += 256)
        wdst[e] = wsrc[e];
    __syncthreads();

    // GEMM: acc[p] = db[j-pair p][i=lane] for jb..jb+7
    const int jb = w * 8;
    unsigned long long acc[4] = {0ull, 0ull, 0ull, 0ull};
    #pragma unroll 4
    for (int ic = 0; ic < IC; ic++) {
        unsigned long long xd = dup2f(xs[ic * CWD + lane]);       // lane-distinct
        const ulonglong2* wp =
            reinterpret_cast<const ulonglong2*>(wrT + ic * J + jb);  // bcast
        ulonglong2 w01 = wp[0], w23 = wp[1];
        FFMA2(acc[0], w01.x, xd);
        FFMA2(acc[1], w01.y, xd);
        FFMA2(acc[2], w23.x, xd);
        FFMA2(acc[3], w23.y, xd);
    }

    // epilogue: coalesced 32-float rows
    #pragma unroll
    for (int p = 0; p < 4; p++) {
        int j = jb + 2 * p;
        float2 dv = unpk(acc[p]);
        float be0 = g_beta[b * J + j];
        float be1 = g_beta[b * J + j + 1];
        size_t o0 = ((size_t)b * J + j) * NPIX + i0g + lane;
        size_t o1 = o0 + NPIX;
        if (it == 1) {
            g_L[o0] = b_init[o0] + dv.x + be0;
            g_L[o1] = b_init[o1] + dv.y + be1;
        } else {
            g_L[o0] += dv.x + be0;
            g_L[o1] += dv.y + be1;
        }
    }
}

// ---------------------------------------------------------------------------
// sy kernel: softmax over j + y GEMM. Grid (4 chunks of 64 px, 64 b) = 256
// CTAs, 512 thr, 97.3KB smem -> 2 CTAs/SM (0.86 wave).
// ---------------------------------------------------------------------------
#define CSP    68
#define XT_O   0                      // xT [i=64][ic=256]   16384
#define CS_O   16384                  // cs [i=64][68]       4352
#define LC_O   (CS_O + CW * CSP)      // Lc [j=64][65]       4160
#define SY_SM_FLOATS (LC_O + J * 65)  // 24896 floats = 99,584 B

__global__ __launch_bounds__(512, 2) void sy_kernel(
    const float* __restrict__ Lsrc, int it)
{
    extern __shared__ float sm[];
    float* xT = sm + XT_O;
    float* cs = sm + CS_O;
    float* Lc = sm + LC_O;

    const int ch   = blockIdx.x;
    const int b    = blockIdx.y;
    const int i0g  = ch * CW;
    const int tid  = threadIdx.x;
    const int w    = tid >> 5;
    const int lane = tid & 31;

    // loads (coalesced)
    const float4* xTb = reinterpret_cast<const float4*>(
        g_xT + ((size_t)b * NPIX + i0g) * IC);
    float4* xTd = reinterpret_cast<float4*>(xT);
    for (int e = tid; e < CW * IC / 4; e += 512)
        xTd[e] = xTb[e];
    for (int e = tid; e < J * CW; e += 512) {
        int j = e >> 6, il = e & 63;
        Lc[j * 65 + il] = Lsrc[((size_t)b * J + j) * NPIX + i0g + il];
    }
    __syncthreads();

    // softmax over j per pixel: 8 threads per pixel, shfl reduce
    {
        int i = tid >> 3, sub = tid & 7, jb2 = sub * 8;
        float m = -1e30f;
        #pragma unroll
        for (int jj = 0; jj < 8; jj++)
            m = fmaxf(m, Lc[(jb2 + jj) * 65 + i]);
        #pragma unroll
        for (int o = 1; o < 8; o <<= 1)
            m = fmaxf(m, __shfl_xor_sync(0xFFFFFFFFu, m, o));
        float ssum = 0.f;
        #pragma unroll
        for (int jj = 0; jj < 8; jj++) {
            float e = __expf(Lc[(jb2 + jj) * 65 + i] - m);
            cs[i * CSP + jb2 + jj] = e;
            ssum += e;
        }
        #pragma unroll
        for (int o = 1; o < 8; o <<= 1)
            ssum += __shfl_xor_sync(0xFFFFFFFFu, ssum, o);
        float rd = 1.0f / ssum;
        #pragma unroll
        for (int jj = 0; jj < 8; jj++)
            cs[i * CSP + jb2 + jj] *= rd;
    }
    __syncthreads();

    // Csum partial per j
    if (tid < J) {
        float cc = 0.f;
        #pragma unroll 8
        for (int i2 = 0; i2 < CW; i2++) cc += cs[i2 * CSP + tid];
        g_cpart[((size_t)b * NCHK + ch) * J + tid] = cc;
    }

    // y GEMM: y[j][ic] = sum_i cs[i][j]*xT[i][ic]; warp=16-ic, lane=j (2 j)
    {
        const int ic0 = w * 16;
        unsigned long long acc[2][8];
        #pragma unroll
        for (int h = 0; h < 2; h++)
            #pragma unroll
            for (int p = 0; p < 8; p++) acc[h][p] = 0ull;

        #pragma unroll 2
        for (int k = 0; k < CW; k++) {
            unsigned long long cd0 = dup2f(cs[k * CSP + lane]);
            unsigned long long cd1 = dup2f(cs[k * CSP + lane + 32]);
            const ulonglong2* xq =
                reinterpret_cast<const ulonglong2*>(xT + k * 256 + ic0);
            ulonglong2 x01 = xq[0], x23 = xq[1], x45 = xq[2], x67 = xq[3];
            FFMA2(acc[0][0], cd0, x01.x); FFMA2(acc[0][1], cd0, x01.y);
            FFMA2(acc[0][2], cd0, x23.x); FFMA2(acc[0][3], cd0, x23.y);
            FFMA2(acc[0][4], cd0, x45.x); FFMA2(acc[0][5], cd0, x45.y);
            FFMA2(acc[0][6], cd0, x67.x); FFMA2(acc[0][7], cd0, x67.y);
            FFMA2(acc[1][0], cd1, x01.x); FFMA2(acc[1][1], cd1, x01.y);
            FFMA2(acc[1][2], cd1, x23.x); FFMA2(acc[1][3], cd1, x23.y);
            FFMA2(acc[1][4], cd1, x45.x); FFMA2(acc[1][5], cd1, x45.y);
            FFMA2(acc[1][6], cd1, x67.x); FFMA2(acc[1][7], cd1, x67.y);
        }
        #pragma unroll
        for (int h = 0; h < 2; h++) {
            int j = lane + 32 * h;
            float* yr = g_ypart + (((size_t)b * NCHK + ch) * J + j) * IC + ic0;
            #pragma unroll
            for (int q = 0; q < 4; q++) {
                float2 e0 = unpk(acc[h][2 * q]);
                float2 e1 = unpk(acc[h][2 * q + 1]);
                *reinterpret_cast<float4*>(yr + 4 * q) =
                    make_float4(e0.x, e0.y, e1.x, e1.y);
            }
        }
    }
}

// ---------------------------------------------------------------------------
// S kernel: one CTA per (j, 16-batch group), 256 threads. Writes g_wtT.
// ---------------------------------------------------------------------------
#define WJ_O2   0
#define YS_O2   8320
#define VS_O2   12480
#define SS_O2   13008
#define CS_O2   13536
#define WB_O2   13552
#define S_SM_FLOATS 13584        // 54,336 B

__global__ __launch_bounds__(256) void s_kernel(
    const float* __restrict__ W, const float* __restrict__ Wb,
    float* __restrict__ out, int final_it)
{
    extern __shared__ float ss[];
    float* Wj  = ss + WJ_O2;
    float* ysm = ss + YS_O2;
    float* vsm = ss + VS_O2;
    float* ssm = ss + SS_O2;
    float* Cs  = ss + CS_O2;
    float* Wbj = ss + WB_O2;

    const int j   = blockIdx.x;
    const int b0  = blockIdx.y * 16;
    const int tid = threadIdx.x;

    for (int e = tid; e < D2 * IC; e += 256) {
        int d = e >> 8, ic = e & 255;
        Wj[d * 260 + ic] = W[(size_t)j * D2 * IC + e];
    }
    if (tid < D2) Wbj[tid] = Wb[j * D2 + tid];
    for (int e = tid; e < 16 * IC; e += 256) {
        int b = e >> 8, ic = e & 255;
        const float* yp = g_ypart + (((size_t)(b0 + b) * NCHK) * J + j) * IC + ic;
        ysm[b * 260 + ic] = (yp[0] + yp[(size_t)J * IC])
                          + (yp[2 * (size_t)J * IC] + yp[3 * (size_t)J * IC]);
    }
    if (tid < 16) {
        const float* cp = g_cpart + ((size_t)(b0 + tid) * NCHK) * J + j;
        Cs[tid] = (cp[0] + cp[J]) + (cp[2 * J] + cp[3 * J]);
    }
    __syncthreads();

    // stage2: s[b][d] = Wj[d,:].y[b,:] + Wb[d]*C[b]
    {
        int b = tid & 15, d0 = (tid >> 4) * 2;
        const float* y  = ysm + b * 260;
        const float* w0 = Wj + d0 * 260;
        const float* w1 = w0 + 260;
        float a0 = 0.f, a1 = 0.f;
        #pragma unroll 8
        for (int ic = 0; ic < IC; ic += 4) {
            float4 y4 = *reinterpret_cast<const float4*>(y + ic);
            float4 wa = *reinterpret_cast<const float4*>(w0 + ic);
            float4 wb = *reinterpret_cast<const float4*>(w1 + ic);
            a0 += y4.x * wa.x + y4.y * wa.y + y4.z * wa.z + y4.w * wa.w;
            a1 += y4.x * wb.x + y4.y * wb.y + y4.z * wb.z + y4.w * wb.w;
        }
        float C = Cs[b];
        ssm[b * 33 + d0]     = a0 + Wbj[d0] * C;
        ssm[b * 33 + d0 + 1] = a1 + Wbj[d0 + 1] * C;
    }
    __syncthreads();

    // squash: warp w handles b = 2w, 2w+1; lane = d
    {
        int w = tid >> 5, lane = tid & 31;
        #pragma unroll
        for (int h = 0; h < 2; h++) {
            int b = w * 2 + h;
            float sv = ssm[b * 33 + lane];
            float sq = sv * sv;
            #pragma unroll
            for (int o = 16; o; o >>= 1) sq += __shfl_xor_sync(0xFFFFFFFFu, sq, o);
            float scale = (sq / (1.0f + sq)) * rsqrtf(sq + 1e-8f);
            float vv = scale * sv;
            vsm[b * 33 + lane] = vv;
            if (final_it) out[((size_t)(b0 + b) * J + j) * D2 + lane] = vv;
            float bt = vv * Wbj[lane];
            #pragma unroll
            for (int o = 16; o; o >>= 1) bt += __shfl_xor_sync(0xFFFFFFFFu, bt, o);
            if (lane == 0) g_beta[(b0 + b) * J + j] = bt;
        }
    }
    __syncthreads();

    // stage4: wtT[b][ic][j] = sum_d v[b][d] * Wj[d][ic]
    if (!final_it) {
        int ic = tid;
        float wv[16];
        #pragma unroll
        for (int b = 0; b < 16; b++) wv[b] = 0.f;
        #pragma unroll 4
        for (int d = 0; d < D2; d++) {
            float wjv = Wj[d * 260 + ic];
            #pragma unroll
            for (int b = 0; b < 16; b++)
                wv[b] = fmaf(vsm[b * 33 + d], wjv, wv[b]);
        }
        #pragma unroll
        for (int b = 0; b < 16; b++)
            g_wtT[((size_t)(b0 + b) * IC + ic) * J + j] = wv[b];
    }
}

// ---------------------------------------------------------------------------
// Launch (9 kernels, graph-capturable, allocation-free)
// Inputs: x[64,256,16,16] f32, b_init[64,64,256] f32, W[2048,256] f32, Wb[2048] f32
// Output: v[64,64,32] f32
// ---------------------------------------------------------------------------
extern "C" void kernel_launch(void* const* d_in, const int* in_sizes, int n_in,
                              void* d_out, int out_size)
{
    const float* x      = (const float*)d_in[0];
    const float* b_init = (const float*)d_in[1];
    const float* W      = (const float*)d_in[2];
    const float* Wb     = (const float*)d_in[3];
    float* out = (float*)d_out;

    const int dbsmem = DB_SM_FLOATS * (int)sizeof(float);  // 98,304 B
    const int sysmem = SY_SM_FLOATS * (int)sizeof(float);  // 99,584 B
    const int ssmem  = S_SM_FLOATS * (int)sizeof(float);   // 54,336 B
    cudaFuncSetAttribute(db_kernel, cudaFuncAttributeMaxDynamicSharedMemorySize, dbsmem);
    cudaFuncSetAttribute(sy_kernel, cudaFuncAttributeMaxDynamicSharedMemorySize, sysmem);
    cudaFuncSetAttribute(s_kernel,  cudaFuncAttributeMaxDynamicSharedMemorySize, ssmem);

    // g_L device-symbol pointer for sy's it>=1 reads
    float* Lwork = nullptr;
    cudaGetSymbolAddress((void**)&Lwork, g_L);

    xt_prep<<<dim3(NPIX / 32, IC / 32, BS), dim3(32, 8)>>>(x);

    dim3 dgrid(NPIX / CWD, BS);   // 8 x 64 = 512 CTAs
    dim3 ygrid(NCHK, BS);         // 4 x 64 = 256 CTAs
    dim3 sgrid(J, 4);             // 64 x 4 = 256 CTAs

    sy_kernel<<<ygrid, 512, sysmem>>>(b_init, 0);
    s_kernel<<<sgrid, 256, ssmem>>>(W, Wb, out, 0);
    db_kernel<<<dgrid, 256, dbsmem>>>(x, b_init, 1);
    sy_kernel<<<ygrid, 512, sysmem>>>(Lwork, 1);
    s_kernel<<<sgrid, 256, ssmem>>>(W, Wb, out, 0);
    db_kernel<<<dgrid, 256, dbsmem>>>(x, b_init, 2);
    sy_kernel<<<ygrid, 512, sysmem>>>(Lwork, 2);
    s_kernel<<<sgrid, 256, ssmem>>>(W, Wb, out, 1);
}

// round 16
// speedup vs baseline: 1.3848x; 1.1467x over previous
#include <cuda_runtime.h>
#include <cstdint>

// Problem constants
#define BS   64
#define IC   256     // in_dim
#define NPIX 256     // pixels (I)
#define J    64      // out caps
#define D2   32      // dim per cap
#define NCHK 4       // i-chunks for sy / ypart
#define CW   64      // sy chunk width
#define CWD  64      // db chunk width (2 px per lane)

// Global scratch
__device__ float g_L[(size_t)BS * J * NPIX];            // working logits
__device__ float g_xT[(size_t)BS * NPIX * IC];          // x transposed [b][i][ic]
__device__ float g_ypart[(size_t)BS * NCHK * J * IC];   // [b][ch][j][ic]
__device__ float g_cpart[(size_t)BS * NCHK * J];        // [b][ch][j]
__device__ float g_wtT[(size_t)BS * IC * J];            // [b][ic][j]
__device__ float g_beta[(size_t)BS * J];                // [b][j]

// ---------------------------------------------------------------------------
// f32x2 helpers
// ---------------------------------------------------------------------------
#define FFMA2(acc, aa, bb) \
    asm("fma.rn.f32x2 %0, %1, %2, %0;" : "+l"(acc) : "l"(aa), "l"(bb))
__device__ __forceinline__ unsigned long long dup2f(float s) {
    unsigned long long d;
    asm("mov.b64 %0, {%1, %1};" : "=l"(d) : "f"(s));
    return d;
}
__device__ __forceinline__ float2 unpk(unsigned long long v) {
    float2 r;
    asm("mov.b64 {%0, %1}, %2;" : "=f"(r.x), "=f"(r.y) : "l"(v));
    return r;
}

// ---------------------------------------------------------------------------
// Prep: transpose x[b][ic][i] -> g_xT[b][i][ic]  (runs once)
// ---------------------------------------------------------------------------
__global__ __launch_bounds__(256) void xt_prep(const float* __restrict__ x) {
    __shared__ float t[32][33];
    int b = blockIdx.z, i0 = blockIdx.x * 32, ic0 = blockIdx.y * 32;
    int tx = threadIdx.x, ty = threadIdx.y;   // 32 x 8
    #pragma unroll
    for (int q = 0; q < 4; q++)
        t[ty + q * 8][tx] = x[((size_t)b * IC + ic0 + ty + q * 8) * NPIX + i0 + tx];
    __syncthreads();
    #pragma unroll
    for (int q = 0; q < 4; q++) {
        int row = ty + q * 8;
        g_xT[((size_t)b * NPIX + i0 + row) * IC + ic0 + tx] = t[tx][row];
    }
}

// ---------------------------------------------------------------------------
// db kernel (it1/it2): Lwork[b,j,i] (+)= sum_ic wtT[ic][j]*x[b,ic,i] + beta.
// Grid (4 chunks of 64 px, 64 b) = 256 CTAs, 256 thr, 64KB smem -> 2/SM,
// ONE wave. x streamed from global via coalesced LDG.64 (2 px per lane);
// wrT broadcast from smem. Inner loop: 1 LDG.64 + 2 LDS.128 + 8 FFMA2.
// ---------------------------------------------------------------------------
#define DB_SM_FLOATS (IC * J)   // wrT[256][64] = 64 KB

__global__ __launch_bounds__(256, 2) void db_kernel(
    const float* __restrict__ x, const float* __restrict__ b_init, int it)
{
    extern __shared__ float wrT[];    // [ic][j]

    const int ch   = blockIdx.x;
    const int b    = blockIdx.y;
    const int i0g  = ch * CWD;
    const int tid  = threadIdx.x;
    const int w    = tid >> 5;
    const int lane = tid & 31;

    // load wrT (float4, coalesced; only smem traffic in this kernel)
    const float4* wsrc = reinterpret_cast<const float4*>(g_wtT + (size_t)b * IC * J);
    float4* wdst = reinterpret_cast<float4*>(wrT);
    for (int e = tid; e < IC * J / 4; e += 256)
        wdst[e] = wsrc[e];
    __syncthreads();

    const int jb = w * 8;             // 8 j per warp
    const int il = 2 * lane;          // 2 pixels per lane
    const float* xp = x + (size_t)b * IC * NPIX + i0g + il;

    unsigned long long acc0[4] = {0ull, 0ull, 0ull, 0ull};   // j-pairs @ px0
    unsigned long long acc1[4] = {0ull, 0ull, 0ull, 0ull};   // j-pairs @ px1
    #pragma unroll 8
    for (int ic = 0; ic < IC; ic++) {
        float2 xv = *reinterpret_cast<const float2*>(xp + (size_t)ic * NPIX);
        unsigned long long xd0 = dup2f(xv.x);
        unsigned long long xd1 = dup2f(xv.y);
        const ulonglong2* wp =
            reinterpret_cast<const ulonglong2*>(wrT + ic * J + jb);  // bcast
        ulonglong2 w01 = wp[0], w23 = wp[1];
        FFMA2(acc0[0], w01.x, xd0); FFMA2(acc1[0], w01.x, xd1);
        FFMA2(acc0[1], w01.y, xd0); FFMA2(acc1[1], w01.y, xd1);
        FFMA2(acc0[2], w23.x, xd0); FFMA2(acc1[2], w23.x, xd1);
        FFMA2(acc0[3], w23.y, xd0); FFMA2(acc1[3], w23.y, xd1);
    }

    // epilogue: float2 rows (coalesced STG.64)
    #pragma unroll
    for (int p = 0; p < 4; p++) {
        int j = jb + 2 * p;
        float2 d0 = unpk(acc0[p]);    // {db[j][px0], db[j+1][px0]}
        float2 d1 = unpk(acc1[p]);    // {db[j][px1], db[j+1][px1]}
        float be0 = g_beta[b * J + j];
        float be1 = g_beta[b * J + j + 1];
        size_t o0 = ((size_t)b * J + j) * NPIX + i0g + il;
        size_t o1 = o0 + NPIX;
        if (it == 1) {
            float2 bi0 = *reinterpret_cast<const float2*>(b_init + o0);
            float2 bi1 = *reinterpret_cast<const float2*>(b_init + o1);
            *reinterpret_cast<float2*>(g_L + o0) =
                make_float2(bi0.x + d0.x + be0, bi0.y + d1.x + be0);
            *reinterpret_cast<float2*>(g_L + o1) =
                make_float2(bi1.x + d0.y + be1, bi1.y + d1.y + be1);
        } else {
            float2 l0 = *reinterpret_cast<const float2*>(g_L + o0);
            float2 l1 = *reinterpret_cast<const float2*>(g_L + o1);
            *reinterpret_cast<float2*>(g_L + o0) =
                make_float2(l0.x + d0.x + be0, l0.y + d1.x + be0);
            *reinterpret_cast<float2*>(g_L + o1) =
                make_float2(l1.x + d0.y + be1, l1.y + d1.y + be1);
        }
    }
}

// ---------------------------------------------------------------------------
// sy kernel: softmax over j + y GEMM. Grid (4 chunks of 64 px, 64 b) = 256
// CTAs, 512 thr, 97.3KB smem -> 2 CTAs/SM. (R15-proven, unchanged.)
// ---------------------------------------------------------------------------
#define CSP    68
#define XT_O   0                      // xT [i=64][ic=256]   16384
#define CS_O   16384                  // cs [i=64][68]       4352
#define LC_O   (CS_O + CW * CSP)      // Lc [j=64][65]       4160
#define SY_SM_FLOATS (LC_O + J * 65)  // 24896 floats = 99,584 B

__global__ __launch_bounds__(512, 2) void sy_kernel(
    const float* __restrict__ Lsrc, int it)
{
    extern __shared__ float sm[];
    float* xT = sm + XT_O;
    float* cs = sm + CS_O;
    float* Lc = sm + LC_O;

    const int ch   = blockIdx.x;
    const int b    = blockIdx.y;
    const int i0g  = ch * CW;
    const int tid  = threadIdx.x;
    const int w    = tid >> 5;
    const int lane = tid & 31;

    const float4* xTb = reinterpret_cast<const float4*>(
        g_xT + ((size_t)b * NPIX + i0g) * IC);
    float4* xTd = reinterpret_cast<float4*>(xT);
    for (int e = tid; e < CW * IC / 4; e += 512)
        xTd[e] = xTb[e];
    for (int e = tid; e < J * CW; e += 512) {
        int j = e >> 6, il = e & 63;
        Lc[j * 65 + il] = Lsrc[((size_t)b * J + j) * NPIX + i0g + il];
    }
    __syncthreads();

    // softmax over j per pixel: 8 threads per pixel, shfl reduce
    {
        int i = tid >> 3, sub = tid & 7, jb2 = sub * 8;
        float m = -1e30f;
        #pragma unroll
        for (int jj = 0; jj < 8; jj++)
            m = fmaxf(m, Lc[(jb2 + jj) * 65 + i]);
        #pragma unroll
        for (int o = 1; o < 8; o <<= 1)
            m = fmaxf(m, __shfl_xor_sync(0xFFFFFFFFu, m, o));
        float ssum = 0.f;
        #pragma unroll
        for (int jj = 0; jj < 8; jj++) {
            float e = __expf(Lc[(jb2 + jj) * 65 + i] - m);
            cs[i * CSP + jb2 + jj] = e;
            ssum += e;
        }
        #pragma unroll
        for (int o = 1; o < 8; o <<= 1)
            ssum += __shfl_xor_sync(0xFFFFFFFFu, ssum, o);
        float rd = 1.0f / ssum;
        #pragma unroll
        for (int jj = 0; jj < 8; jj++)
            cs[i * CSP + jb2 + jj] *= rd;
    }
    __syncthreads();

    // Csum partial per j
    if (tid < J) {
        float cc = 0.f;
        #pragma unroll 8
        for (int i2 = 0; i2 < CW; i2++) cc += cs[i2 * CSP + tid];
        g_cpart[((size_t)b * NCHK + ch) * J + tid] = cc;
    }

    // y GEMM: y[j][ic] = sum_i cs[i][j]*xT[i][ic]; warp=16-ic, lane=j (2 j)
    {
        const int ic0 = w * 16;
        unsigned long long acc[2][8];
        #pragma unroll
        for (int h = 0; h < 2; h++)
            #pragma unroll
            for (int p = 0; p < 8; p++) acc[h][p] = 0ull;

        #pragma unroll 2
        for (int k = 0; k < CW; k++) {
            unsigned long long cd0 = dup2f(cs[k * CSP + lane]);
            unsigned long long cd1 = dup2f(cs[k * CSP + lane + 32]);
            const ulonglong2* xq =
                reinterpret_cast<const ulonglong2*>(xT + k * 256 + ic0);
            ulonglong2 x01 = xq[0], x23 = xq[1], x45 = xq[2], x67 = xq[3];
            FFMA2(acc[0][0], cd0, x01.x); FFMA2(acc[0][1], cd0, x01.y);
            FFMA2(acc[0][2], cd0, x23.x); FFMA2(acc[0][3], cd0, x23.y);
            FFMA2(acc[0][4], cd0, x45.x); FFMA2(acc[0][5], cd0, x45.y);
            FFMA2(acc[0][6], cd0, x67.x); FFMA2(acc[0][7], cd0, x67.y);
            FFMA2(acc[1][0], cd1, x01.x); FFMA2(acc[1][1], cd1, x01.y);
            FFMA2(acc[1][2], cd1, x23.x); FFMA2(acc[1][3], cd1, x23.y);
            FFMA2(acc[1][4], cd1, x45.x); FFMA2(acc[1][5], cd1, x45.y);
            FFMA2(acc[1][6], cd1, x67.x); FFMA2(acc[1][7], cd1, x67.y);
        }
        #pragma unroll
        for (int h = 0; h < 2; h++) {
            int j = lane + 32 * h;
            float* yr = g_ypart + (((size_t)b * NCHK + ch) * J + j) * IC + ic0;
            #pragma unroll
            for (int q = 0; q < 4; q++) {
                float2 e0 = unpk(acc[h][2 * q]);
                float2 e1 = unpk(acc[h][2 * q + 1]);
                *reinterpret_cast<float4*>(yr + 4 * q) =
                    make_float4(e0.x, e0.y, e1.x, e1.y);
            }
        }
    }
}

// ---------------------------------------------------------------------------
// S kernel: one CTA per (j, 16-batch group), 256 threads. Writes g_wtT.
// ---------------------------------------------------------------------------
#define WJ_O2   0
#define YS_O2   8320
#define VS_O2   12480
#define SS_O2   13008
#define CS_O2   13536
#define WB_O2   13552
#define S_SM_FLOATS 13584        // 54,336 B

__global__ __launch_bounds__(256) void s_kernel(
    const float* __restrict__ W, const float* __restrict__ Wb,
    float* __restrict__ out, int final_it)
{
    extern __shared__ float ss[];
    float* Wj  = ss + WJ_O2;
    float* ysm = ss + YS_O2;
    float* vsm = ss + VS_O2;
    float* ssm = ss + SS_O2;
    float* Cs  = ss + CS_O2;
    float* Wbj = ss + WB_O2;

    const int j   = blockIdx.x;
    const int b0  = blockIdx.y * 16;
    const int tid = threadIdx.x;

    for (int e = tid; e < D2 * IC; e += 256) {
        int d = e >> 8, ic = e & 255;
        Wj[d * 260 + ic] = W[(size_t)j * D2 * IC + e];
    }
    if (tid < D2) Wbj[tid] = Wb[j * D2 + tid];
    for (int e = tid; e < 16 * IC; e += 256) {
        int b = e >> 8, ic = e & 255;
        const float* yp = g_ypart + (((size_t)(b0 + b) * NCHK) * J + j) * IC + ic;
        ysm[b * 260 + ic] = (yp[0] + yp[(size_t)J * IC])
                          + (yp[2 * (size_t)J * IC] + yp[3 * (size_t)J * IC]);
    }
    if (tid < 16) {
        const float* cp = g_cpart + ((size_t)(b0 + tid) * NCHK) * J + j;
        Cs[tid] = (cp[0] + cp[J]) + (cp[2 * J] + cp[3 * J]);
    }
    __syncthreads();

    // stage2: s[b][d] = Wj[d,:].y[b,:] + Wb[d]*C[b]
    {
        int b = tid & 15, d0 = (tid >> 4) * 2;
        const float* y  = ysm + b * 260;
        const float* w0 = Wj + d0 * 260;
        const float* w1 = w0 + 260;
        float a0 = 0.f, a1 = 0.f;
        #pragma unroll 8
        for (int ic = 0; ic < IC; ic += 4) {
            float4 y4 = *reinterpret_cast<const float4*>(y + ic);
            float4 wa = *reinterpret_cast<const float4*>(w0 + ic);
            float4 wb = *reinterpret_cast<const float4*>(w1 + ic);
            a0 += y4.x * wa.x + y4.y * wa.y + y4.z * wa.z + y4.w * wa.w;
            a1 += y4.x * wb.x + y4.y * wb.y + y4.z * wb.z + y4.w * wb.w;
        }
        float C = Cs[b];
        ssm[b * 33 + d0]     = a0 + Wbj[d0] * C;
        ssm[b * 33 + d0 + 1] = a1 + Wbj[d0 + 1] * C;
    }
    __syncthreads();

    // squash: warp w handles b = 2w, 2w+1; lane = d
    {
        int w = tid >> 5, lane = tid & 31;
        #pragma unroll
        for (int h = 0; h < 2; h++) {
            int b = w * 2 + h;
            float sv = ssm[b * 33 + lane];
            float sq = sv * sv;
            #pragma unroll
            for (int o = 16; o; o >>= 1) sq += __shfl_xor_sync(0xFFFFFFFFu, sq, o);
            float scale = (sq / (1.0f + sq)) * rsqrtf(sq + 1e-8f);
            float vv = scale * sv;
            vsm[b * 33 + lane] = vv;
            if (final_it) out[((size_t)(b0 + b) * J + j) * D2 + lane] = vv;
            float bt = vv * Wbj[lane];
            #pragma unroll
            for (int o = 16; o; o >>= 1) bt += __shfl_xor_sync(0xFFFFFFFFu, bt, o);
            if (lane == 0) g_beta[(b0 + b) * J + j] = bt;
        }
    }
    __syncthreads();

    // stage4: wtT[b][ic][j] = sum_d v[b][d] * Wj[d][ic]
    if (!final_it) {
        int ic = tid;
        float wv[16];
        #pragma unroll
        for (int b = 0; b < 16; b++) wv[b] = 0.f;
        #pragma unroll 4
        for (int d = 0; d < D2; d++) {
            float wjv = Wj[d * 260 + ic];
            #pragma unroll
            for (int b = 0; b < 16; b++)
                wv[b] = fmaf(vsm[b * 33 + d], wjv, wv[b]);
        }
        #pragma unroll
        for (int b = 0; b < 16; b++)
            g_wtT[((size_t)(b0 + b) * IC + ic) * J + j] = wv[b];
    }
}

// ---------------------------------------------------------------------------
// Launch (9 kernels, graph-capturable, allocation-free)
// Inputs: x[64,256,16,16] f32, b_init[64,64,256] f32, W[2048,256] f32, Wb[2048] f32
// Output: v[64,64,32] f32
// ---------------------------------------------------------------------------
extern "C" void kernel_launch(void* const* d_in, const int* in_sizes, int n_in,
                              void* d_out, int out_size)
{
    const float* x      = (const float*)d_in[0];
    const float* b_init = (const float*)d_in[1];
    const float* W      = (const float*)d_in[2];
    const float* Wb     = (const float*)d_in[3];
    float* out = (float*)d_out;

    const int dbsmem = DB_SM_FLOATS * (int)sizeof(float);  // 65,536 B
    const int sysmem = SY_SM_FLOATS * (int)sizeof(float);  // 99,584 B
    const int ssmem  = S_SM_FLOATS * (int)sizeof(float);   // 54,336 B
    cudaFuncSetAttribute(db_kernel, cudaFuncAttributeMaxDynamicSharedMemorySize, dbsmem);
    cudaFuncSetAttribute(sy_kernel, cudaFuncAttributeMaxDynamicSharedMemorySize, sysmem);
    cudaFuncSetAttribute(s_kernel,  cudaFuncAttributeMaxDynamicSharedMemorySize, ssmem);

    float* Lwork = nullptr;
    cudaGetSymbolAddress((void**)&Lwork, g_L);

    xt_prep<<<dim3(NPIX / 32, IC / 32, BS), dim3(32, 8)>>>(x);

    dim3 dgrid(NPIX / CWD, BS);   // 4 x 64 = 256 CTAs, one wave
    dim3 ygrid(NCHK, BS);         // 4 x 64 = 256 CTAs
    dim3 sgrid(J, 4);             // 64 x 4 = 256 CTAs

    sy_kernel<<<ygrid, 512, sysmem>>>(b_init, 0);
    s_kernel<<<sgrid, 256, ssmem>>>(W, Wb, out, 0);
    db_kernel<<<dgrid, 256, dbsmem>>>(x, b_init, 1);
    sy_kernel<<<ygrid, 512, sysmem>>>(Lwork, 1);
    s_kernel<<<sgrid, 256, ssmem>>>(W, Wb, out, 0);
    db_kernel<<<dgrid, 256, dbsmem>>>(x, b_init, 2);
    sy_kernel<<<ygrid, 512, sysmem>>>(Lwork, 2);
    s_kernel<<<sgrid, 256, ssmem>>>(W, Wb, out, 1);
}